// round 16
// baseline (speedup 1.0000x reference)
#include <cuda_runtime.h>
#include <math.h>
#include <float.h>

#define TLEN 8192
#define NT   256
#define PERT 32            // TLEN / NT
#define NW   (NT / 32)     // 8 warps
#define NQ   (TLEN / 4)    // 2048 float4 per row
#define EPSF 1e-8f

// SMEM staging pad: 1 float4 per 8 float4s. Conflict-free for coalesced
// STS.128 (q = j*NT+tid) and per-thread-contiguous LDS.128 (q = tid*8+j).
__device__ __forceinline__ int pad4(int q) { return q + (q >> 3); }

// ---- packed f32x2 helpers (sm_103a: add/mul/fma.rn.f32x2 only) ------------
__device__ __forceinline__ unsigned long long pk2(float lo, float hi) {
    unsigned long long d;
    asm("mov.b64 %0, {%1, %2};" : "=l"(d)
        : "r"(__float_as_uint(lo)), "r"(__float_as_uint(hi)));
    return d;
}
__device__ __forceinline__ void upk2(float& lo, float& hi, unsigned long long s) {
    unsigned int a, b;
    asm("mov.b64 {%0, %1}, %2;" : "=r"(a), "=r"(b) : "l"(s));
    lo = __uint_as_float(a); hi = __uint_as_float(b);
}
__device__ __forceinline__ unsigned long long add2(unsigned long long a,
                                                   unsigned long long b) {
    unsigned long long d;
    asm("add.rn.f32x2 %0, %1, %2;" : "=l"(d) : "l"(a), "l"(b));
    return d;
}

// Scales (T=8192): {256,512,1024,2048,4096}; chunks {32,16,8,4,2}.
// Thread owns 32 contiguous elems; chunk 256 = 8 lanes, 512 = 16 lanes,
// 1024 = 1 warp, 2048 = 2 warps, 4096 = 4 warps.

__global__ void __launch_bounds__(NT, 6)          // 42-reg target -> 48 warps/SM
hurst_kernel(const float* __restrict__ x, float* __restrict__ out,
             float c0, float c1, float c2, float c3, float c4,
             float inv_den)
{
    __shared__ float4 stage[NQ + (NQ >> 3)];   // 36,864 B
    __shared__ float Pb[32];                   // prefixes at 256-boundaries
    __shared__ float warpTot[NW];
    __shared__ float ssW_s[NW];                // per-warp (1024-elem) sumsq
    __shared__ float wMax[2][NW];              // warp partials for k=3,4
    __shared__ float wMin[2][NW];
    __shared__ float rs_sum[5];

    const int tid  = threadIdx.x;
    const int wid  = tid >> 5;
    const int lane = tid & 31;
    const float4* __restrict__ xr4 =
        reinterpret_cast<const float4*>(x + (size_t)blockIdx.x * TLEN);

    if (tid < 5) rs_sum[tid] = 0.0f;

    // ---- coalesced load -> padded SMEM stage ------------------------------
    #pragma unroll
    for (int j = 0; j < 8; ++j) {
        const int q = j * NT + tid;            // warp: 512B contiguous
        stage[pad4(q)] = xr4[q];
    }
    __syncthreads();

    // ---- per-thread contiguous 32 elems from stage ------------------------
    float v[PERT];
    #pragma unroll
    for (int j = 0; j < 8; ++j) {
        const float4 t = stage[pad4(tid * 8 + j)];
        v[j*4+0] = t.x; v[j*4+1] = t.y; v[j*4+2] = t.z; v[j*4+3] = t.w;
    }

    float ss = 0.0f;
    #pragma unroll
    for (int j = 0; j < PERT; ++j) ss = fmaf(v[j], v[j], ss);

    // serial inclusive scan, split into two independent 16-chains + merge
    #pragma unroll
    for (int j = 1; j < 16; ++j) v[j] += v[j - 1];
    #pragma unroll
    for (int j = 17; j < 32; ++j) v[j] += v[j - 1];
    const float lo_tot = v[15];
    #pragma unroll
    for (int j = 16; j < 32; ++j) v[j] += lo_tot;
    const float tot = v[PERT - 1];

    // warp inclusive scan of per-thread totals
    float incl = tot;
    #pragma unroll
    for (int d = 1; d < 32; d <<= 1) {
        float n = __shfl_up_sync(0xffffffffu, incl, d);
        if (lane >= d) incl += n;
    }
    const float exclWarp = incl - tot;
    if (lane == 31) warpTot[wid] = incl;

    // ss reductions: 8-lane (256), 16-lane (512), warp (1024)
    float ss8 = ss;
    #pragma unroll
    for (int m = 1; m <= 4; m <<= 1) ss8 += __shfl_xor_sync(0xffffffffu, ss8, m);
    const float ss16 = ss8  + __shfl_xor_sync(0xffffffffu, ss8, 8);
    const float ssW  = ss16 + __shfl_xor_sync(0xffffffffu, ss16, 16);

    __syncthreads();
    if (tid < NW) {                      // scan 8 warp totals -> exclusive
        float t  = warpTot[tid];
        float i2 = t;
        #pragma unroll
        for (int d = 1; d < 8; d <<= 1) {
            float n = __shfl_up_sync(0x000000ffu, i2, d);
            if (tid >= d) i2 += n;
        }
        warpTot[tid] = i2 - t;
    }
    __syncthreads();
    const float off  = warpTot[wid] + exclWarp;
    const int   base = tid * PERT;
    const float fb1  = (float)(base + 1);

    // publish the 32 boundary prefixes + per-warp sumsq
    if ((tid & 7) == 7) Pb[tid >> 3] = v[PERT - 1] + off;
    if (lane == 0)      ssW_s[wid]   = ssW;
    __syncthreads();

    // pack off-adjusted prefixes; consume v pairwise so ptxas can overlay
    // each v[2p],v[2p+1] register pair with wv2[p].
    unsigned long long wv2[16];
    {
        const unsigned long long off2 = pk2(off, off);
        #pragma unroll
        for (int p = 0; p < 16; ++p) {
            wv2[p] = add2(pk2(v[2*p], v[2*p + 1]), off2);
        }
    }

    // ---- per-scale sweeps: packed adds + scalar FMNMX ---------------------
    // u_j = (v[j]+off) - (base+j+1)*mean ; per-chunk shift drops out of R.
    #pragma unroll
    for (int k = 0; k < 5; ++k) {
        const int s      = 256 << k;                 // compile-time
        const int cstart = base & ~(s - 1);
        const int bidx   = cstart >> 8;
        const float Pprev = (cstart == 0) ? 0.0f : Pb[bidx - 1];
        const float Pend  = Pb[bidx + (1 << k) - 1];
        const float mean  = (Pend - Pprev) * (1.0f / (float)s);

        const float t0 = fb1 * mean;
        unsigned long long nt2 = pk2(-t0, -(t0 + mean));
        const unsigned long long nd2 = pk2(-2.0f * mean, -2.0f * mean);
        float mx = -FLT_MAX, mn = FLT_MAX;
        #pragma unroll
        for (int p = 0; p < 16; ++p) {
            const unsigned long long u2 = add2(wv2[p], nt2);
            float ul, uh;  upk2(ul, uh, u2);     // free: register-pair halves
            mx = fmaxf(mx, ul);  mn = fminf(mn, ul);
            mx = fmaxf(mx, uh);  mn = fminf(mn, uh);
            nt2 = add2(nt2, nd2);
        }

        if (k == 0) {                // chunk == 8 lanes
            #pragma unroll
            for (int m = 1; m <= 4; m <<= 1) {
                mx = fmaxf(mx, __shfl_xor_sync(0xffffffffu, mx, m));
                mn = fminf(mn, __shfl_xor_sync(0xffffffffu, mn, m));
            }
            if ((tid & 7) == 0) {
                const float R   = mx - mn;
                const float var = fmaxf(ss8 - 256.0f * mean * mean, 0.0f)
                                  * (1.0f / 255.0f);
                const float S   = fmaxf(sqrtf(var), EPSF);
                atomicAdd(&rs_sum[0], fmaxf(R / S, EPSF));
            }
        } else if (k == 1) {         // chunk == 16 lanes
            #pragma unroll
            for (int m = 1; m <= 8; m <<= 1) {
                mx = fmaxf(mx, __shfl_xor_sync(0xffffffffu, mx, m));
                mn = fminf(mn, __shfl_xor_sync(0xffffffffu, mn, m));
            }
            if ((tid & 15) == 0) {
                const float R   = mx - mn;
                const float var = fmaxf(ss16 - 512.0f * mean * mean, 0.0f)
                                  * (1.0f / 511.0f);
                const float S   = fmaxf(sqrtf(var), EPSF);
                atomicAdd(&rs_sum[1], fmaxf(R / S, EPSF));
            }
        } else if (k == 2) {         // chunk == warp
            #pragma unroll
            for (int m = 1; m <= 16; m <<= 1) {
                mx = fmaxf(mx, __shfl_xor_sync(0xffffffffu, mx, m));
                mn = fminf(mn, __shfl_xor_sync(0xffffffffu, mn, m));
            }
            if (lane == 0) {
                const float R   = mx - mn;
                const float var = fmaxf(ssW - 1024.0f * mean * mean, 0.0f)
                                  * (1.0f / 1023.0f);
                const float S   = fmaxf(sqrtf(var), EPSF);
                atomicAdd(&rs_sum[2], fmaxf(R / S, EPSF));
            }
        } else {                     // chunk spans warps: publish warp partials
            #pragma unroll
            for (int m = 1; m <= 16; m <<= 1) {
                mx = fmaxf(mx, __shfl_xor_sync(0xffffffffu, mx, m));
                mn = fminf(mn, __shfl_xor_sync(0xffffffffu, mn, m));
            }
            if (lane == 0) { wMax[k - 3][wid] = mx; wMin[k - 3][wid] = mn; }
        }
    }
    __syncthreads();

    // ---- combine k=3,4 (4+2 = 6 chunks), one thread per chunk -------------
    if (tid < 6) {
        int k, cc, nwarp;
        if (tid < 4) { k = 3; cc = tid;     nwarp = 2; }
        else         { k = 4; cc = tid - 4; nwarp = 4; }
        const int w0 = cc * nwarp;
        float mx = -FLT_MAX, mn = FLT_MAX, ssC = 0.0f;
        for (int w = 0; w < nwarp; ++w) {
            mx   = fmaxf(mx, wMax[k - 3][w0 + w]);
            mn   = fminf(mn, wMin[k - 3][w0 + w]);
            ssC += ssW_s[w0 + w];
        }
        const int s  = 256 << k;
        const int bi = cc << k;
        const float P0 = (cc == 0) ? 0.0f : Pb[bi - 1];
        const float P1 = Pb[bi + (1 << k) - 1];
        const float mk = (P1 - P0) / (float)s;
        const float var = fmaxf(ssC - (float)s * mk * mk, 0.0f) / (float)(s - 1);
        const float S   = fmaxf(sqrtf(var), EPSF);
        atomicAdd(&rs_sum[k], fmaxf((mx - mn) / S, EPSF));
    }
    __syncthreads();

    // ---- log-log slope + clip ---------------------------------------------
    if (tid == 0) {
        const float lnc[5] = {c0, c1, c2, c3, c4};
        const float ncs[5] = {32.0f, 16.0f, 8.0f, 4.0f, 2.0f};
        float num = 0.0f;
        #pragma unroll
        for (int k = 0; k < 5; ++k)
            num += lnc[k] * logf(fmaxf(rs_sum[k] * (1.0f / ncs[k]), EPSF));
        float H = num * inv_den;
        H = fminf(fmaxf(H, 0.05f), 0.95f);
        out[blockIdx.x] = H;
    }
}

extern "C" void kernel_launch(void* const* d_in, const int* in_sizes, int n_in,
                              void* d_out, int out_size)
{
    (void)n_in; (void)in_sizes;
    const float* x = (const float*)d_in[0];
    float* out = (float*)d_out;
    const int B = out_size;              // 4096 rows (T fixed at 8192)

    // centered log-scales + 1/den for scales {256,512,1024,2048,4096}
    double ln[5], meanln = 0.0;
    for (int k = 0; k < 5; ++k) { ln[k] = log((double)(256 << k)); meanln += ln[k]; }
    meanln /= 5.0;
    double den = 0.0;
    float lnc[5];
    for (int k = 0; k < 5; ++k) {
        double c = ln[k] - meanln;
        lnc[k] = (float)c;
        den += c * c;
    }
    if (den < 1e-8) den = 1e-8;
    const float inv_den = (float)(1.0 / den);

    hurst_kernel<<<B, NT>>>(x, out, lnc[0], lnc[1], lnc[2], lnc[3], lnc[4],
                            inv_den);
}

// round 17
// speedup vs baseline: 1.4045x; 1.4045x over previous
#include <cuda_runtime.h>
#include <math.h>
#include <float.h>

#define TLEN 8192
#define NT   256
#define PERT 32            // TLEN / NT
#define NW   (NT / 32)     // 8 warps
#define NQ   (TLEN / 4)    // 2048 float4 per row
#define EPSF 1e-8f

// SMEM staging pad: 1 float4 per 8 float4s. Conflict-free for coalesced
// STS.128 (q = j*NT+tid) and per-thread-contiguous LDS.128 (q = tid*8+j).
__device__ __forceinline__ int pad4(int q) { return q + (q >> 3); }

// ---- packed f32x2 helpers (sm_103a: add/mul/fma.rn.f32x2 only) ------------
__device__ __forceinline__ unsigned long long pk2(float lo, float hi) {
    unsigned long long d;
    asm("mov.b64 %0, {%1, %2};" : "=l"(d)
        : "r"(__float_as_uint(lo)), "r"(__float_as_uint(hi)));
    return d;
}
__device__ __forceinline__ void upk2(float& lo, float& hi, unsigned long long s) {
    unsigned int a, b;
    asm("mov.b64 {%0, %1}, %2;" : "=r"(a), "=r"(b) : "l"(s));
    lo = __uint_as_float(a); hi = __uint_as_float(b);
}
__device__ __forceinline__ unsigned long long add2(unsigned long long a,
                                                   unsigned long long b) {
    unsigned long long d;
    asm("add.rn.f32x2 %0, %1, %2;" : "=l"(d) : "l"(a), "l"(b));
    return d;
}

// Scales (T=8192): {256,512,1024,2048,4096}; chunks {32,16,8,4,2}.
// Thread owns 32 contiguous elems; chunk 256 = 8 lanes, 512 = 16 lanes,
// 1024 = 1 warp, 2048 = 2 warps, 4096 = 4 warps.

__global__ void __launch_bounds__(NT, 5)          // R15 trunk: regs 48, 5 CTAs
hurst_kernel(const float* __restrict__ x, float* __restrict__ out,
             float c0, float c1, float c2, float c3, float c4,
             float inv_den)
{
    __shared__ float4 stage[NQ + (NQ >> 3)];   // 36,864 B
    __shared__ float Pb[32];                   // prefixes at 256-boundaries
    __shared__ float warpTot[NW];
    __shared__ float ssW_s[NW];                // per-warp (1024-elem) sumsq
    __shared__ float wMax[2][NW];              // warp partials for k=3,4
    __shared__ float wMin[2][NW];
    __shared__ float rs_sum[5];

    const int tid  = threadIdx.x;
    const int wid  = tid >> 5;
    const int lane = tid & 31;
    const float4* __restrict__ xr4 =
        reinterpret_cast<const float4*>(x + (size_t)blockIdx.x * TLEN);

    if (tid < 5) rs_sum[tid] = 0.0f;

    // ---- coalesced load -> padded SMEM stage ------------------------------
    #pragma unroll
    for (int j = 0; j < 8; ++j) {
        const int q = j * NT + tid;            // warp: 512B contiguous
        stage[pad4(q)] = xr4[q];
    }
    __syncthreads();

    // ---- per-thread contiguous 32 elems from stage ------------------------
    float v[PERT];
    #pragma unroll
    for (int j = 0; j < 8; ++j) {
        const float4 t = stage[pad4(tid * 8 + j)];
        v[j*4+0] = t.x; v[j*4+1] = t.y; v[j*4+2] = t.z; v[j*4+3] = t.w;
    }

    float ss = 0.0f;
    #pragma unroll
    for (int j = 0; j < PERT; ++j) ss = fmaf(v[j], v[j], ss);
    #pragma unroll
    for (int j = 1; j < PERT; ++j) v[j] += v[j - 1];
    const float tot = v[PERT - 1];

    // warp inclusive scan of per-thread totals
    float incl = tot;
    #pragma unroll
    for (int d = 1; d < 32; d <<= 1) {
        float n = __shfl_up_sync(0xffffffffu, incl, d);
        if (lane >= d) incl += n;
    }
    const float exclWarp = incl - tot;
    if (lane == 31) warpTot[wid] = incl;

    // ss reductions: 8-lane (256), 16-lane (512), warp (1024)
    float ss8 = ss;
    #pragma unroll
    for (int m = 1; m <= 4; m <<= 1) ss8 += __shfl_xor_sync(0xffffffffu, ss8, m);
    const float ss16 = ss8  + __shfl_xor_sync(0xffffffffu, ss8, 8);
    const float ssW  = ss16 + __shfl_xor_sync(0xffffffffu, ss16, 16);

    __syncthreads();
    if (tid < NW) {                      // scan 8 warp totals -> exclusive
        float t  = warpTot[tid];
        float i2 = t;
        #pragma unroll
        for (int d = 1; d < 8; d <<= 1) {
            float n = __shfl_up_sync(0x000000ffu, i2, d);
            if (tid >= d) i2 += n;
        }
        warpTot[tid] = i2 - t;
    }
    __syncthreads();
    const float off  = warpTot[wid] + exclWarp;
    const int   base = tid * PERT;
    const float fb1  = (float)(base + 1);

    // publish the 32 boundary prefixes + per-warp sumsq
    if ((tid & 7) == 7) Pb[tid >> 3] = v[PERT - 1] + off;
    if (lane == 0)      ssW_s[wid]   = ssW;
    __syncthreads();

    // pack off-adjusted prefixes into 16 f32x2 registers (v dead afterwards)
    unsigned long long wv2[16];
    {
        const unsigned long long off2 = pk2(off, off);
        #pragma unroll
        for (int p = 0; p < 16; ++p)
            wv2[p] = add2(pk2(v[2*p], v[2*p + 1]), off2);
    }

    // ---- per-scale sweeps: packed adds + scalar FMNMX ---------------------
    // u_j = (v[j]+off) - (base+j+1)*mean ; per-chunk shift drops out of R.
    #pragma unroll
    for (int k = 0; k < 5; ++k) {
        const int s      = 256 << k;                 // compile-time
        const int cstart = base & ~(s - 1);
        const int bidx   = cstart >> 8;
        const float Pprev = (cstart == 0) ? 0.0f : Pb[bidx - 1];
        const float Pend  = Pb[bidx + (1 << k) - 1];
        const float mean  = (Pend - Pprev) * (1.0f / (float)s);

        const float t0 = fb1 * mean;
        unsigned long long nt2 = pk2(-t0, -(t0 + mean));
        const unsigned long long nd2 = pk2(-2.0f * mean, -2.0f * mean);
        float mx = -FLT_MAX, mn = FLT_MAX;
        #pragma unroll
        for (int p = 0; p < 16; ++p) {
            const unsigned long long u2 = add2(wv2[p], nt2);
            float ul, uh;  upk2(ul, uh, u2);     // free: register-pair halves
            mx = fmaxf(mx, ul);  mn = fminf(mn, ul);
            mx = fmaxf(mx, uh);  mn = fminf(mn, uh);
            nt2 = add2(nt2, nd2);
        }

        if (k == 0) {                // chunk == 8 lanes
            #pragma unroll
            for (int m = 1; m <= 4; m <<= 1) {
                mx = fmaxf(mx, __shfl_xor_sync(0xffffffffu, mx, m));
                mn = fminf(mn, __shfl_xor_sync(0xffffffffu, mn, m));
            }
            // every lane now holds its 8-lane group's mx/mn -> valid rs
            const float var = fmaxf(ss8 - 256.0f * mean * mean, 0.0f)
                              * (1.0f / 255.0f);
            const float S   = fmaxf(sqrtf(var), EPSF);
            float contrib = ((tid & 7) == 0) ? fmaxf((mx - mn) / S, EPSF) : 0.0f;
            contrib += __shfl_xor_sync(0xffffffffu, contrib, 8);
            contrib += __shfl_xor_sync(0xffffffffu, contrib, 16);
            if (lane == 0) atomicAdd(&rs_sum[0], contrib);   // 1 atomic/warp
        } else if (k == 1) {         // chunk == 16 lanes
            #pragma unroll
            for (int m = 1; m <= 8; m <<= 1) {
                mx = fmaxf(mx, __shfl_xor_sync(0xffffffffu, mx, m));
                mn = fminf(mn, __shfl_xor_sync(0xffffffffu, mn, m));
            }
            const float var = fmaxf(ss16 - 512.0f * mean * mean, 0.0f)
                              * (1.0f / 511.0f);
            const float S   = fmaxf(sqrtf(var), EPSF);
            float contrib = ((tid & 15) == 0) ? fmaxf((mx - mn) / S, EPSF) : 0.0f;
            contrib += __shfl_xor_sync(0xffffffffu, contrib, 16);
            if (lane == 0) atomicAdd(&rs_sum[1], contrib);   // 1 atomic/warp
        } else if (k == 2) {         // chunk == warp
            #pragma unroll
            for (int m = 1; m <= 16; m <<= 1) {
                mx = fmaxf(mx, __shfl_xor_sync(0xffffffffu, mx, m));
                mn = fminf(mn, __shfl_xor_sync(0xffffffffu, mn, m));
            }
            if (lane == 0) {
                const float R   = mx - mn;
                const float var = fmaxf(ssW - 1024.0f * mean * mean, 0.0f)
                                  * (1.0f / 1023.0f);
                const float S   = fmaxf(sqrtf(var), EPSF);
                atomicAdd(&rs_sum[2], fmaxf(R / S, EPSF));
            }
        } else {                     // chunk spans warps: publish warp partials
            #pragma unroll
            for (int m = 1; m <= 16; m <<= 1) {
                mx = fmaxf(mx, __shfl_xor_sync(0xffffffffu, mx, m));
                mn = fminf(mn, __shfl_xor_sync(0xffffffffu, mn, m));
            }
            if (lane == 0) { wMax[k - 3][wid] = mx; wMin[k - 3][wid] = mn; }
        }
    }
    __syncthreads();

    // ---- combine k=3,4 (4+2 = 6 chunks), one thread per chunk -------------
    if (tid < 6) {
        int k, cc, nwarp;
        if (tid < 4) { k = 3; cc = tid;     nwarp = 2; }
        else         { k = 4; cc = tid - 4; nwarp = 4; }
        const int w0 = cc * nwarp;
        float mx = -FLT_MAX, mn = FLT_MAX, ssC = 0.0f;
        for (int w = 0; w < nwarp; ++w) {
            mx   = fmaxf(mx, wMax[k - 3][w0 + w]);
            mn   = fminf(mn, wMin[k - 3][w0 + w]);
            ssC += ssW_s[w0 + w];
        }
        const int s  = 256 << k;
        const int bi = cc << k;
        const float P0 = (cc == 0) ? 0.0f : Pb[bi - 1];
        const float P1 = Pb[bi + (1 << k) - 1];
        const float mk = (P1 - P0) / (float)s;
        const float var = fmaxf(ssC - (float)s * mk * mk, 0.0f) / (float)(s - 1);
        const float S   = fmaxf(sqrtf(var), EPSF);
        atomicAdd(&rs_sum[k], fmaxf((mx - mn) / S, EPSF));
    }
    __syncthreads();

    // ---- log-log slope + clip ---------------------------------------------
    if (tid == 0) {
        const float lnc[5] = {c0, c1, c2, c3, c4};
        const float ncs[5] = {32.0f, 16.0f, 8.0f, 4.0f, 2.0f};
        float num = 0.0f;
        #pragma unroll
        for (int k = 0; k < 5; ++k)
            num += lnc[k] * logf(fmaxf(rs_sum[k] * (1.0f / ncs[k]), EPSF));
        float H = num * inv_den;
        H = fminf(fmaxf(H, 0.05f), 0.95f);
        out[blockIdx.x] = H;
    }
}

extern "C" void kernel_launch(void* const* d_in, const int* in_sizes, int n_in,
                              void* d_out, int out_size)
{
    (void)n_in; (void)in_sizes;
    const float* x = (const float*)d_in[0];
    float* out = (float*)d_out;
    const int B = out_size;              // 4096 rows (T fixed at 8192)

    // centered log-scales + 1/den for scales {256,512,1024,2048,4096}
    double ln[5], meanln = 0.0;
    for (int k = 0; k < 5; ++k) { ln[k] = log((double)(256 << k)); meanln += ln[k]; }
    meanln /= 5.0;
    double den = 0.0;
    float lnc[5];
    for (int k = 0; k < 5; ++k) {
        double c = ln[k] - meanln;
        lnc[k] = (float)c;
        den += c * c;
    }
    if (den < 1e-8) den = 1e-8;
    const float inv_den = (float)(1.0 / den);

    hurst_kernel<<<B, NT>>>(x, out, lnc[0], lnc[1], lnc[2], lnc[3], lnc[4],
                            inv_den);
}